// round 13
// baseline (speedup 1.0000x reference)
#include <cuda_runtime.h>
#include <cuda_bf16.h>
#include <cstdint>
#include <math.h>

// Shapes (fixed)
#define Bsz 8
#define Sq  2048
#define Dd  512
#define Hh  512
#define MS  (Bsz * Sq)   // 16384

// ---------------- scratch (device globals) ----------------
__device__ __nv_bfloat16 g_xb  [(long)MS * Dd];
__device__ __nv_bfloat16 g_qk  [(long)MS * 1024];    // q cols 0-511 | k cols 512-1023
__device__ __nv_bfloat16 g_vTb [(long)MS * Hh];      // [Hh, MS]
__device__ __nv_bfloat16 g_ctxb[(long)MS * Hh];
__device__ __nv_bfloat16 g_p   [(long)Bsz * Sq * Sq]; // unnormalized probs (bf16)
__device__ float         g_lsum[MS];                   // per-row exp sums
__device__ __nv_bfloat16 g_wqkt[1024 * Dd];            // WqT | WkT
__device__ __nv_bfloat16 g_wvt[Dd * Hh];
__device__ __nv_bfloat16 g_wot[Dd * Hh];
__device__ float         g_bqk[1024];

// ---------------- helpers ----------------
__device__ __forceinline__ uint32_t smem_u32(const void* p) {
    uint32_t a;
    asm("{ .reg .u64 t; cvta.to.shared.u64 t, %1; cvt.u32.u64 %0, t; }" : "=r"(a) : "l"(p));
    return a;
}
#define LDSM4(r, a)                                                              \
    asm volatile("ldmatrix.sync.aligned.m8n8.x4.shared.b16 {%0,%1,%2,%3}, [%4];" \
                 : "=r"((r)[0]), "=r"((r)[1]), "=r"((r)[2]), "=r"((r)[3])        \
                 : "r"(a))
__device__ __forceinline__ void mma_bf16(float* c, const uint32_t* a,
                                         uint32_t b0, uint32_t b1) {
    asm volatile(
        "mma.sync.aligned.m16n8k16.row.col.f32.bf16.bf16.f32 "
        "{%0,%1,%2,%3}, {%4,%5,%6,%7}, {%8,%9}, {%0,%1,%2,%3};"
        : "+f"(c[0]), "+f"(c[1]), "+f"(c[2]), "+f"(c[3])
        : "r"(a[0]), "r"(a[1]), "r"(a[2]), "r"(a[3]), "r"(b0), "r"(b1));
}
#define CP_ASYNC(dst, src) \
    asm volatile("cp.async.cg.shared.global [%0], [%1], 16;" :: "r"(dst), "l"(src))
#define CP_COMMIT() asm volatile("cp.async.commit_group;" ::: "memory")
#define CP_WAIT(n)  asm volatile("cp.async.wait_group %0;" :: "n"(n) : "memory")

// ============================================================================
// Persistent bf16 NT GEMM with fused epilogues.
// 296 CTAs loop over flattened (z, ni, mi) tiles; 3-stage cp.async pipeline
// runs continuously across tile boundaries (prologue paid once per CTA).
// BM=BN=128, BK=64, 128 threads (2x2 warps, 64x64 warp tiles).
// ============================================================================
#define RS 144
#define B_OFF  (128 * RS)
#define STAGE  (256 * RS)
#define NSTAGE 3
#define GSMEM_TOTAL (NSTAGE * STAGE)
#define NPERSIST 296

__device__ __forceinline__ void stage_load(
    uint32_t sbase, const __nv_bfloat16* __restrict__ A, long lda,
    const __nv_bfloat16* __restrict__ B, long ldb, int m0, int n0, int kt, int t)
{
    const int lrow = t >> 3, lch = t & 7;
#pragma unroll
    for (int i = 0; i < 8; i++) {
        const int row = lrow + i * 16;
        CP_ASYNC(sbase + row * RS + lch * 16,
                 A + (long)(m0 + row) * lda + kt + lch * 8);
    }
#pragma unroll
    for (int i = 0; i < 8; i++) {
        const int row = lrow + i * 16;
        CP_ASYNC(sbase + B_OFF + row * RS + lch * 16,
                 B + (long)(n0 + row) * ldb + kt + lch * 8);
    }
}

__global__ __launch_bounds__(128, 2) void gemm_persist(
    const __nv_bfloat16* __restrict__ A, long lda, long sA,
    const __nv_bfloat16* __restrict__ B, long ldb, long sB,
    void* __restrict__ Cv, long ldc, long sC,
    const float* __restrict__ biasN, const float* __restrict__ biasM,
    const float* __restrict__ res,
    float* __restrict__ rowsum, const float* __restrict__ rowdiv, long rsStride,
    float alpha, int K, int c_bf16,
    int tilesM, int tilesN, int ntiles)
{
    extern __shared__ __align__(128) char smem[];
    const uint32_t sb = smem_u32(smem);
    const int t = threadIdx.x;
    const int TMN = tilesM * tilesN;
    const int nch = K / 64;

    const int lane = t & 31, w = t >> 5;
    const int wm = w & 1, wn = w >> 1;
    const uint32_t aB = sb + (wm * 64 + (lane & 15)) * RS + (lane >> 4) * 16;
    const uint32_t bB = sb + B_OFF + (wn * 64 + (lane & 15)) * RS + (lane >> 4) * 16;
    const int gcol0 = (lane & 3) * 2;
    const int grow  = lane >> 2;

    float acc[4][8][4];
#pragma unroll
    for (int i = 0; i < 4; i++)
#pragma unroll
        for (int j = 0; j < 8; j++)
#pragma unroll
            for (int r = 0; r < 4; r++) acc[i][j][r] = 0.f;

    // load cursor (tl, kl) and compute cursor (tc, kc)
    int tl = blockIdx.x, kl = 0;
    int tc = blockIdx.x, kc = 0;
    int gload = 0;

#define LOAD_CHUNK() do {                                                   \
        const int z_ = tl / TMN;                                            \
        const int rem_ = tl - z_ * TMN;                                     \
        const int mi_ = rem_ % tilesM, ni_ = rem_ / tilesM;                 \
        stage_load(sb + (gload % NSTAGE) * STAGE,                           \
                   A + (long)z_ * sA, lda, B + (long)z_ * sB, ldb,          \
                   mi_ * 128, ni_ * 128, kl * 64, t);                       \
        gload++;                                                            \
        if (++kl == nch) { kl = 0; tl += gridDim.x; }                       \
    } while (0)

    // prologue: first two chunks
#pragma unroll 1
    for (int i = 0; i < 2; i++) {
        if (tl < ntiles) LOAD_CHUNK();
        CP_COMMIT();
    }
    if (tc >= ntiles) return;
    CP_WAIT(1);
    __syncthreads();

    int gcomp = 0;
#pragma unroll 1
    while (true) {
        if (tl < ntiles) LOAD_CHUNK();
        CP_COMMIT();

        // MMA on chunk gcomp (buffer gcomp % 3)
        const uint32_t so = (gcomp % NSTAGE) * STAGE;
#pragma unroll
        for (int s = 0; s < 4; s++) {
            uint32_t af[4][4], bf[4][4];
#pragma unroll
            for (int mt = 0; mt < 4; mt++)
                LDSM4(af[mt], aB + so + mt * (16 * RS) + s * 32);
#pragma unroll
            for (int p = 0; p < 4; p++)
                LDSM4(bf[p], bB + so + p * (16 * RS) + s * 32);
#pragma unroll
            for (int mt = 0; mt < 4; mt++)
#pragma unroll
                for (int p = 0; p < 4; p++) {
                    mma_bf16(acc[mt][2 * p + 0], af[mt], bf[p][0], bf[p][2]);
                    mma_bf16(acc[mt][2 * p + 1], af[mt], bf[p][1], bf[p][3]);
                }
        }
        gcomp++;

        CP_WAIT(1);
        __syncthreads();

        if (++kc == nch) {
            // ---- epilogue for tile tc ----
            const int z = tc / TMN;
            const int rem = tc - z * TMN;
            const int mi = rem % tilesM, ni = rem / tilesM;
            const int m0 = mi * 128, n0 = ni * 128;
            const float* resz = res ? res + (long)z * sC : nullptr;
            float* rsumz = rowsum ? rowsum + (long)z * rsStride : nullptr;
            const float* rdivz = rowdiv ? rowdiv + (long)z * rsStride : nullptr;

            if (rsumz) {
                __nv_bfloat16* C = (__nv_bfloat16*)Cv + (long)z * sC;
#pragma unroll
                for (int mt = 0; mt < 4; mt++) {
                    const long row = m0 + wm * 64 + mt * 16 + grow;
                    float rs0 = 0.f, rs1 = 0.f;
#pragma unroll
                    for (int nt = 0; nt < 8; nt++) {
                        const int col = n0 + wn * 64 + nt * 8 + gcol0;
                        const float e00 = __expf(acc[mt][nt][0] * alpha);
                        const float e01 = __expf(acc[mt][nt][1] * alpha);
                        const float e10 = __expf(acc[mt][nt][2] * alpha);
                        const float e11 = __expf(acc[mt][nt][3] * alpha);
                        rs0 += e00 + e01;
                        rs1 += e10 + e11;
                        *(__nv_bfloat162*)(C + row * ldc + col) =
                            __float22bfloat162_rn(make_float2(e00, e01));
                        *(__nv_bfloat162*)(C + (row + 8) * ldc + col) =
                            __float22bfloat162_rn(make_float2(e10, e11));
                    }
                    rs0 += __shfl_xor_sync(0xffffffffu, rs0, 1);
                    rs0 += __shfl_xor_sync(0xffffffffu, rs0, 2);
                    rs1 += __shfl_xor_sync(0xffffffffu, rs1, 1);
                    rs1 += __shfl_xor_sync(0xffffffffu, rs1, 2);
                    if ((lane & 3) == 0) {
                        atomicAdd(rsumz + row, rs0);
                        atomicAdd(rsumz + row + 8, rs1);
                    }
                }
            } else {
#pragma unroll
                for (int mt = 0; mt < 4; mt++) {
                    const long row = m0 + wm * 64 + mt * 16 + grow;
                    const float bm0 = biasM ? biasM[row] : 0.f;
                    const float bm1 = biasM ? biasM[row + 8] : 0.f;
                    const float iv0 = rdivz ? __fdividef(1.f, rdivz[row]) : 1.f;
                    const float iv1 = rdivz ? __fdividef(1.f, rdivz[row + 8]) : 1.f;
#pragma unroll
                    for (int nt = 0; nt < 8; nt++) {
                        const int col = n0 + wn * 64 + nt * 8 + gcol0;
                        float2 v0, v1;
                        v0.x = acc[mt][nt][0] * alpha * iv0 + bm0;
                        v0.y = acc[mt][nt][1] * alpha * iv0 + bm0;
                        v1.x = acc[mt][nt][2] * alpha * iv1 + bm1;
                        v1.y = acc[mt][nt][3] * alpha * iv1 + bm1;
                        if (biasN) {
                            const float2 bb = *(const float2*)(biasN + col);
                            v0.x += bb.x; v0.y += bb.y; v1.x += bb.x; v1.y += bb.y;
                        }
                        if (resz) {
                            const float2 r0 = *(const float2*)(resz + row * ldc + col);
                            const float2 r1 = *(const float2*)(resz + (row + 8) * ldc + col);
                            v0.x += r0.x; v0.y += r0.y; v1.x += r1.x; v1.y += r1.y;
                        }
                        if (c_bf16) {
                            __nv_bfloat16* C = (__nv_bfloat16*)Cv + (long)z * sC;
                            *(__nv_bfloat162*)(C + row * ldc + col) = __float22bfloat162_rn(v0);
                            *(__nv_bfloat162*)(C + (row + 8) * ldc + col) = __float22bfloat162_rn(v1);
                        } else {
                            float* C = (float*)Cv + (long)z * sC;
                            *(float2*)(C + row * ldc + col) = v0;
                            *(float2*)(C + (row + 8) * ldc + col) = v1;
                        }
                    }
                }
            }

            kc = 0;
            tc += gridDim.x;
            if (tc >= ntiles) break;
#pragma unroll
            for (int i = 0; i < 4; i++)
#pragma unroll
                for (int j = 0; j < 8; j++)
#pragma unroll
                    for (int r = 0; r < 4; r++) acc[i][j][r] = 0.f;
        }
    }
#undef LOAD_CHUNK
}

// ---------------- 4x 512x512 transpose -> bf16, one launch ----------------
struct TPtrs {
    const float* w[4];
    __nv_bfloat16* wt[4];
};
__global__ __launch_bounds__(256) void transpose_all(TPtrs p)
{
    const float* W = p.w[blockIdx.z];
    __nv_bfloat16* Wt = p.wt[blockIdx.z];
    __shared__ float tile[32][33];
    const int tx = threadIdx.x, ty = threadIdx.y;
    int x = blockIdx.x * 32 + tx;
    int y = blockIdx.y * 32 + ty;
#pragma unroll
    for (int i = 0; i < 4; i++)
        tile[ty + i * 8][tx] = W[(y + i * 8) * 512 + x];
    __syncthreads();
    x = blockIdx.y * 32 + tx;
    y = blockIdx.x * 32 + ty;
#pragma unroll
    for (int i = 0; i < 4; i++)
        Wt[(y + i * 8) * 512 + x] = __float2bfloat16_rn(tile[tx][ty + i * 8]);
}

// ---------------- prep: cvt x -> bf16, zero lsum, concat biases ----------------
__global__ __launch_bounds__(256) void prep_misc(
    const float* __restrict__ in, __nv_bfloat16* __restrict__ out, long n4,
    float* __restrict__ zbuf, long zn,
    const float* __restrict__ bq, const float* __restrict__ bk,
    float* __restrict__ bqk)
{
    const long i = (long)blockIdx.x * blockDim.x + threadIdx.x;
    if (i < n4) {
        float4 v = ((const float4*)in)[i];
        *(__nv_bfloat162*)(out + i * 4)     = __float22bfloat162_rn(make_float2(v.x, v.y));
        *(__nv_bfloat162*)(out + i * 4 + 2) = __float22bfloat162_rn(make_float2(v.z, v.w));
    }
    if (i < zn) zbuf[i] = 0.f;
    if (i < 1024) bqk[i] = (i < 512) ? bq[i] : bk[i - 512];
}

// ---------------- launch ----------------
extern "C" void kernel_launch(void* const* d_in, const int* in_sizes, int n_in,
                              void* d_out, int out_size)
{
    const float* x  = (const float*)d_in[0];
    const float* Wq = (const float*)d_in[1];
    const float* bq = (const float*)d_in[2];
    const float* Wk = (const float*)d_in[3];
    const float* bk = (const float*)d_in[4];
    const float* Wv = (const float*)d_in[5];
    const float* bv = (const float*)d_in[6];
    const float* Wo = (const float*)d_in[7];
    const float* bo = (const float*)d_in[8];
    float* out = (float*)d_out;

    __nv_bfloat16 *xb, *qk, *vTb, *ctxb, *pb, *wqkt, *wvt, *wot;
    float *lsum, *bqk;
    cudaGetSymbolAddress((void**)&xb,   g_xb);
    cudaGetSymbolAddress((void**)&qk,   g_qk);
    cudaGetSymbolAddress((void**)&vTb,  g_vTb);
    cudaGetSymbolAddress((void**)&ctxb, g_ctxb);
    cudaGetSymbolAddress((void**)&pb,   g_p);
    cudaGetSymbolAddress((void**)&lsum, g_lsum);
    cudaGetSymbolAddress((void**)&wqkt, g_wqkt);
    cudaGetSymbolAddress((void**)&wvt,  g_wvt);
    cudaGetSymbolAddress((void**)&wot,  g_wot);
    cudaGetSymbolAddress((void**)&bqk,  g_bqk);

    static int init = 0;
    if (!init) {
        cudaFuncSetAttribute(gemm_persist,
                             cudaFuncAttributeMaxDynamicSharedMemorySize, GSMEM_TOTAL);
        init = 1;
    }

    const float inv_sqrt_h = 1.f / sqrtf((float)Hh);

    // 0) prep
    {
        TPtrs tp;
        tp.w[0] = Wq; tp.w[1] = Wk; tp.w[2] = Wv; tp.w[3] = Wo;
        tp.wt[0] = wqkt; tp.wt[1] = wqkt + 512 * 512; tp.wt[2] = wvt; tp.wt[3] = wot;
        transpose_all<<<dim3(16, 16, 4), dim3(32, 8)>>>(tp);
        const long n4 = (long)MS * Dd / 4;
        prep_misc<<<(n4 + 255) / 256, 256>>>(x, xb, n4, lsum, MS, bq, bk, bqk);
    }

    // 1) qk = x @ [Wq|Wk] (+bqk) -> bf16. tiles: M=128, N=8 -> 1024
    gemm_persist<<<NPERSIST, 128, GSMEM_TOTAL>>>(
        xb, Dd, 0, wqkt, Dd, 0, qk, 1024, 0, bqk, nullptr, nullptr,
        nullptr, nullptr, 0, 1.f, Dd, 1, MS / 128, 1024 / 128, 1024);

    // 2) vT = (x @ Wv + bv)^T -> bf16. tiles: M=4, N=128 -> 512
    gemm_persist<<<NPERSIST, 128, GSMEM_TOTAL>>>(
        wvt, Dd, 0, xb, Dd, 0, vTb, MS, 0, nullptr, bv, nullptr,
        nullptr, nullptr, 0, 1.f, Dd, 1, Hh / 128, MS / 128, 512);

    // 3) P = exp(q k^T / sqrt(H)) -> bf16, row sums. tiles: 16x16x8 -> 2048
    gemm_persist<<<NPERSIST, 128, GSMEM_TOTAL>>>(
        qk, 1024, (long)Sq * 1024, qk + 512, 1024, (long)Sq * 1024,
        pb, Sq, (long)Sq * Sq, nullptr, nullptr, nullptr,
        lsum, nullptr, Sq, inv_sqrt_h, Hh, 1, Sq / 128, Sq / 128, 2048);

    // 4) ctx = (P @ V) / lsum -> bf16. tiles: 16x4x8 -> 512, K=2048
    gemm_persist<<<NPERSIST, 128, GSMEM_TOTAL>>>(
        pb, Sq, (long)Sq * Sq, vTb, MS, Sq, ctxb, Hh, (long)Sq * Hh,
        nullptr, nullptr, nullptr, nullptr, lsum, Sq,
        1.f, Sq, 1, Sq / 128, Hh / 128, 512);

    // 5) out = ctx @ Wo + bo + x -> fp32. tiles: 128x4 -> 512
    gemm_persist<<<NPERSIST, 128, GSMEM_TOTAL>>>(
        ctxb, Hh, 0, wot, Hh, 0, out, Dd, 0, bo, nullptr, x,
        nullptr, nullptr, 0, 1.f, Hh, 0, MS / 128, Dd / 128, 512);
}

// round 14
// speedup vs baseline: 1.2163x; 1.2163x over previous
#include <cuda_runtime.h>
#include <cuda_bf16.h>
#include <cstdint>
#include <math.h>

// Shapes (fixed)
#define Bsz 8
#define Sq  2048
#define Dd  512
#define Hh  512
#define MS  (Bsz * Sq)   // 16384

// ---------------- scratch (device globals) ----------------
__device__ __nv_bfloat16 g_xb  [(long)MS * Dd];
__device__ __nv_bfloat16 g_qk  [(long)MS * 1024];    // q cols 0-511 | k cols 512-1023
__device__ __nv_bfloat16 g_vTb [(long)MS * Hh];      // [Hh, MS]
__device__ __nv_bfloat16 g_ctxb[(long)MS * Hh];
__device__ __nv_bfloat16 g_p   [(long)Bsz * Sq * Sq]; // unnormalized probs (bf16)
__device__ float         g_lsum[MS];                   // per-row exp sums
__device__ __nv_bfloat16 g_wqkt[1024 * Dd];            // WqT | WkT
__device__ __nv_bfloat16 g_wvt[Dd * Hh];
__device__ __nv_bfloat16 g_wot[Dd * Hh];
__device__ float         g_bqk[1024];

// ---------------- helpers ----------------
__device__ __forceinline__ uint32_t smem_u32(const void* p) {
    uint32_t a;
    asm("{ .reg .u64 t; cvta.to.shared.u64 t, %1; cvt.u32.u64 %0, t; }" : "=r"(a) : "l"(p));
    return a;
}
#define LDSM4(r, a)                                                              \
    asm volatile("ldmatrix.sync.aligned.m8n8.x4.shared.b16 {%0,%1,%2,%3}, [%4];" \
                 : "=r"((r)[0]), "=r"((r)[1]), "=r"((r)[2]), "=r"((r)[3])        \
                 : "r"(a))
__device__ __forceinline__ void mma_bf16(float* c, const uint32_t* a,
                                         uint32_t b0, uint32_t b1) {
    asm volatile(
        "mma.sync.aligned.m16n8k16.row.col.f32.bf16.bf16.f32 "
        "{%0,%1,%2,%3}, {%4,%5,%6,%7}, {%8,%9}, {%0,%1,%2,%3};"
        : "+f"(c[0]), "+f"(c[1]), "+f"(c[2]), "+f"(c[3])
        : "r"(a[0]), "r"(a[1]), "r"(a[2]), "r"(a[3]), "r"(b0), "r"(b1));
}
#define CP_ASYNC(dst, src) \
    asm volatile("cp.async.cg.shared.global [%0], [%1], 16;" :: "r"(dst), "l"(src))
#define CP_COMMIT() asm volatile("cp.async.commit_group;" ::: "memory")
#define CP_WAIT(n)  asm volatile("cp.async.wait_group %0;" :: "n"(n) : "memory")

// ============================================================================
// bf16 NT GEMM with fused epilogues (R10/R12 core, unchanged).
// BM=BN=128, BK=64, 128 threads (2x2 warps, 64x64 tiles), 3-stage pipeline.
// ============================================================================
#define RS 144
#define B_OFF  (128 * RS)
#define STAGE  (256 * RS)
#define NSTAGE 3
#define GSMEM_TOTAL (NSTAGE * STAGE)

__device__ __forceinline__ void stage_load(
    uint32_t sbase, const __nv_bfloat16* __restrict__ A, long lda,
    const __nv_bfloat16* __restrict__ B, long ldb, int m0, int n0, int kt, int t)
{
    const int lrow = t >> 3, lch = t & 7;
#pragma unroll
    for (int i = 0; i < 8; i++) {
        const int row = lrow + i * 16;
        CP_ASYNC(sbase + row * RS + lch * 16,
                 A + (long)(m0 + row) * lda + kt + lch * 8);
    }
#pragma unroll
    for (int i = 0; i < 8; i++) {
        const int row = lrow + i * 16;
        CP_ASYNC(sbase + B_OFF + row * RS + lch * 16,
                 B + (long)(n0 + row) * ldb + kt + lch * 8);
    }
}

__global__ __launch_bounds__(128, 2) void gemm_bf16_nt(
    const __nv_bfloat16* __restrict__ A, long lda, long sA,
    const __nv_bfloat16* __restrict__ B, long ldb, long sB,
    void* __restrict__ Cv, long ldc, long sC,
    const float* __restrict__ biasN, const float* __restrict__ biasM,
    const float* __restrict__ res,
    float* __restrict__ rowsum, const float* __restrict__ rowdiv, long rsStride,
    float alpha, int K, int c_bf16)
{
    extern __shared__ __align__(128) char smem[];
    const uint32_t sb = smem_u32(smem);
    const int t = threadIdx.x;
    const int m0 = blockIdx.x * 128;
    const int n0 = blockIdx.y * 128;

    A += (long)blockIdx.z * sA;
    B += (long)blockIdx.z * sB;
    const float* resz = res ? res + (long)blockIdx.z * sC : nullptr;
    float* rsumz = rowsum ? rowsum + (long)blockIdx.z * rsStride : nullptr;
    const float* rdivz = rowdiv ? rowdiv + (long)blockIdx.z * rsStride : nullptr;

    const int lane = t & 31, w = t >> 5;
    const int wm = w & 1, wn = w >> 1;

    const uint32_t aB = sb + (wm * 64 + (lane & 15)) * RS + (lane >> 4) * 16;
    const uint32_t bB = sb + B_OFF + (wn * 64 + (lane & 15)) * RS + (lane >> 4) * 16;

    float acc[4][8][4];
#pragma unroll
    for (int i = 0; i < 4; i++)
#pragma unroll
        for (int j = 0; j < 8; j++)
#pragma unroll
            for (int r = 0; r < 4; r++) acc[i][j][r] = 0.f;

    const int ktiles = K / 64;
    stage_load(sb, A, lda, B, ldb, m0, n0, 0, t);
    CP_COMMIT();
    if (ktiles > 1) stage_load(sb + STAGE, A, lda, B, ldb, m0, n0, 64, t);
    CP_COMMIT();
    CP_WAIT(1);
    __syncthreads();

    for (int kt = 0; kt < ktiles; kt++) {
        if (kt + 2 < ktiles)
            stage_load(sb + ((kt + 2) % NSTAGE) * STAGE, A, lda, B, ldb,
                       m0, n0, (kt + 2) * 64, t);
        CP_COMMIT();

        const uint32_t so = (kt % NSTAGE) * STAGE;
#pragma unroll
        for (int s = 0; s < 4; s++) {
            uint32_t af[4][4], bf[4][4];
#pragma unroll
            for (int mt = 0; mt < 4; mt++)
                LDSM4(af[mt], aB + so + mt * (16 * RS) + s * 32);
#pragma unroll
            for (int p = 0; p < 4; p++)
                LDSM4(bf[p], bB + so + p * (16 * RS) + s * 32);
#pragma unroll
            for (int mt = 0; mt < 4; mt++)
#pragma unroll
                for (int p = 0; p < 4; p++) {
                    mma_bf16(acc[mt][2 * p + 0], af[mt], bf[p][0], bf[p][2]);
                    mma_bf16(acc[mt][2 * p + 1], af[mt], bf[p][1], bf[p][3]);
                }
        }

        CP_WAIT(1);
        __syncthreads();
    }

    const int gcol0 = (lane & 3) * 2;
    const int grow  = lane >> 2;

    if (rsumz) {
        __nv_bfloat16* C = (__nv_bfloat16*)Cv + (long)blockIdx.z * sC;
#pragma unroll
        for (int mt = 0; mt < 4; mt++) {
            const long row = m0 + wm * 64 + mt * 16 + grow;
            float rs0 = 0.f, rs1 = 0.f;
#pragma unroll
            for (int nt = 0; nt < 8; nt++) {
                const int col = n0 + wn * 64 + nt * 8 + gcol0;
                const float e00 = __expf(acc[mt][nt][0] * alpha);
                const float e01 = __expf(acc[mt][nt][1] * alpha);
                const float e10 = __expf(acc[mt][nt][2] * alpha);
                const float e11 = __expf(acc[mt][nt][3] * alpha);
                rs0 += e00 + e01;
                rs1 += e10 + e11;
                *(__nv_bfloat162*)(C + row * ldc + col) =
                    __float22bfloat162_rn(make_float2(e00, e01));
                *(__nv_bfloat162*)(C + (row + 8) * ldc + col) =
                    __float22bfloat162_rn(make_float2(e10, e11));
            }
            rs0 += __shfl_xor_sync(0xffffffffu, rs0, 1);
            rs0 += __shfl_xor_sync(0xffffffffu, rs0, 2);
            rs1 += __shfl_xor_sync(0xffffffffu, rs1, 1);
            rs1 += __shfl_xor_sync(0xffffffffu, rs1, 2);
            if ((lane & 3) == 0) {
                atomicAdd(rsumz + row, rs0);
                atomicAdd(rsumz + row + 8, rs1);
            }
        }
        return;
    }

#pragma unroll
    for (int mt = 0; mt < 4; mt++) {
        const long row = m0 + wm * 64 + mt * 16 + grow;
        const float bm0 = biasM ? biasM[row] : 0.f;
        const float bm1 = biasM ? biasM[row + 8] : 0.f;
        const float iv0 = rdivz ? __fdividef(1.f, rdivz[row]) : 1.f;
        const float iv1 = rdivz ? __fdividef(1.f, rdivz[row + 8]) : 1.f;
#pragma unroll
        for (int nt = 0; nt < 8; nt++) {
            const int col = n0 + wn * 64 + nt * 8 + gcol0;
            float2 v0, v1;
            v0.x = acc[mt][nt][0] * alpha * iv0 + bm0;
            v0.y = acc[mt][nt][1] * alpha * iv0 + bm0;
            v1.x = acc[mt][nt][2] * alpha * iv1 + bm1;
            v1.y = acc[mt][nt][3] * alpha * iv1 + bm1;
            if (biasN) {
                const float2 bb = *(const float2*)(biasN + col);
                v0.x += bb.x; v0.y += bb.y; v1.x += bb.x; v1.y += bb.y;
            }
            if (resz) {
                const float2 r0 = *(const float2*)(resz + row * ldc + col);
                const float2 r1 = *(const float2*)(resz + (row + 8) * ldc + col);
                v0.x += r0.x; v0.y += r0.y; v1.x += r1.x; v1.y += r1.y;
            }
            if (c_bf16) {
                __nv_bfloat16* C = (__nv_bfloat16*)Cv + (long)blockIdx.z * sC;
                *(__nv_bfloat162*)(C + row * ldc + col) = __float22bfloat162_rn(v0);
                *(__nv_bfloat162*)(C + (row + 8) * ldc + col) = __float22bfloat162_rn(v1);
            } else {
                float* C = (float*)Cv + (long)blockIdx.z * sC;
                *(float2*)(C + row * ldc + col) = v0;
                *(float2*)(C + (row + 8) * ldc + col) = v1;
            }
        }
    }
}

// ---------------- 4x 512x512 transpose -> bf16, one launch ----------------
struct TPtrs {
    const float* w[4];
    __nv_bfloat16* wt[4];
};
__global__ __launch_bounds__(256) void transpose_all(TPtrs p)
{
    const float* W = p.w[blockIdx.z];
    __nv_bfloat16* Wt = p.wt[blockIdx.z];
    __shared__ float tile[32][33];
    const int tx = threadIdx.x, ty = threadIdx.y;
    int x = blockIdx.x * 32 + tx;
    int y = blockIdx.y * 32 + ty;
#pragma unroll
    for (int i = 0; i < 4; i++)
        tile[ty + i * 8][tx] = W[(y + i * 8) * 512 + x];
    __syncthreads();
    x = blockIdx.y * 32 + tx;
    y = blockIdx.x * 32 + ty;
#pragma unroll
    for (int i = 0; i < 4; i++)
        Wt[(y + i * 8) * 512 + x] = __float2bfloat16_rn(tile[tx][ty + i * 8]);
}

// ---------------- prep: cvt x -> bf16, zero lsum, concat biases ----------------
__global__ __launch_bounds__(256) void prep_misc(
    const float* __restrict__ in, __nv_bfloat16* __restrict__ out, long n4,
    float* __restrict__ zbuf, long zn,
    const float* __restrict__ bq, const float* __restrict__ bk,
    float* __restrict__ bqk)
{
    const long i = (long)blockIdx.x * blockDim.x + threadIdx.x;
    if (i < n4) {
        float4 v = ((const float4*)in)[i];
        *(__nv_bfloat162*)(out + i * 4)     = __float22bfloat162_rn(make_float2(v.x, v.y));
        *(__nv_bfloat162*)(out + i * 4 + 2) = __float22bfloat162_rn(make_float2(v.z, v.w));
    }
    if (i < zn) zbuf[i] = 0.f;
    if (i < 1024) bqk[i] = (i < 512) ? bq[i] : bk[i - 512];
}

// ---------------- launch ----------------
extern "C" void kernel_launch(void* const* d_in, const int* in_sizes, int n_in,
                              void* d_out, int out_size)
{
    const float* x  = (const float*)d_in[0];
    const float* Wq = (const float*)d_in[1];
    const float* bq = (const float*)d_in[2];
    const float* Wk = (const float*)d_in[3];
    const float* bk = (const float*)d_in[4];
    const float* Wv = (const float*)d_in[5];
    const float* bv = (const float*)d_in[6];
    const float* Wo = (const float*)d_in[7];
    const float* bo = (const float*)d_in[8];
    float* out = (float*)d_out;

    __nv_bfloat16 *xb, *qk, *vTb, *ctxb, *pb, *wqkt, *wvt, *wot;
    float *lsum, *bqk;
    cudaGetSymbolAddress((void**)&xb,   g_xb);
    cudaGetSymbolAddress((void**)&qk,   g_qk);
    cudaGetSymbolAddress((void**)&vTb,  g_vTb);
    cudaGetSymbolAddress((void**)&ctxb, g_ctxb);
    cudaGetSymbolAddress((void**)&pb,   g_p);
    cudaGetSymbolAddress((void**)&lsum, g_lsum);
    cudaGetSymbolAddress((void**)&wqkt, g_wqkt);
    cudaGetSymbolAddress((void**)&wvt,  g_wvt);
    cudaGetSymbolAddress((void**)&wot,  g_wot);
    cudaGetSymbolAddress((void**)&bqk,  g_bqk);

    static cudaStream_t s1 = nullptr, s2 = nullptr;
    static cudaEvent_t evPrep, evV, evB;
    if (!s1) {
        cudaFuncSetAttribute(gemm_bf16_nt,
                             cudaFuncAttributeMaxDynamicSharedMemorySize, GSMEM_TOTAL);
        cudaStreamCreateWithFlags(&s1, cudaStreamNonBlocking);
        cudaStreamCreateWithFlags(&s2, cudaStreamNonBlocking);
        cudaEventCreateWithFlags(&evPrep, cudaEventDisableTiming);
        cudaEventCreateWithFlags(&evV,    cudaEventDisableTiming);
        cudaEventCreateWithFlags(&evB,    cudaEventDisableTiming);
    }

    const float inv_sqrt_h = 1.f / sqrtf((float)Hh);
    const long HB = 4;                  // batches per half
    const long xoffB  = HB * Sq * Dd;
    const long qkoffB = HB * Sq * 1024;
    const long poffB  = HB * Sq * Sq;
    const long coffB  = HB * Sq * Hh;

    // ---- prep on stream 0 ----
    {
        TPtrs tp;
        tp.w[0] = Wq; tp.w[1] = Wk; tp.w[2] = Wv; tp.w[3] = Wo;
        tp.wt[0] = wqkt; tp.wt[1] = wqkt + 512 * 512; tp.wt[2] = wvt; tp.wt[3] = wot;
        transpose_all<<<dim3(16, 16, 4), dim3(32, 8)>>>(tp);
        const long n4 = (long)MS * Dd / 4;
        prep_misc<<<(n4 + 255) / 256, 256>>>(x, xb, n4, lsum, MS, bq, bk, bqk);
    }
    cudaEventRecord(evPrep, 0);
    cudaStreamWaitEvent(s1, evPrep, 0);
    cudaStreamWaitEvent(s2, evPrep, 0);

    // ---- projections: qkA on s0, qkB on s1, vT on s2 (all concurrent) ----
    // qkA: batches 0-3 (512 CTAs)
    gemm_bf16_nt<<<dim3(HB * Sq / 128, 1024 / 128, 1), 128, GSMEM_TOTAL>>>(
        xb, Dd, 0, wqkt, Dd, 0, qk, 1024, 0, bqk, nullptr, nullptr,
        nullptr, nullptr, 0, 1.f, Dd, 1);
    // qkB: batches 4-7 (512 CTAs)
    gemm_bf16_nt<<<dim3(HB * Sq / 128, 1024 / 128, 1), 128, GSMEM_TOTAL, s1>>>(
        xb + xoffB, Dd, 0, wqkt, Dd, 0, qk + qkoffB, 1024, 0, bqk, nullptr, nullptr,
        nullptr, nullptr, 0, 1.f, Dd, 1);
    // vT (512 CTAs)
    gemm_bf16_nt<<<dim3(Hh / 128, MS / 128, 1), 128, GSMEM_TOTAL, s2>>>(
        wvt, Dd, 0, xb, Dd, 0, vTb, MS, 0, nullptr, bv, nullptr,
        nullptr, nullptr, 0, 1.f, Dd, 1);
    cudaEventRecord(evV, s2);

    // ---- scores (stream-local after qk halves) ----
    gemm_bf16_nt<<<dim3(Sq / 128, Sq / 128, HB), 128, GSMEM_TOTAL>>>(
        qk, 1024, (long)Sq * 1024, qk + 512, 1024, (long)Sq * 1024,
        pb, Sq, (long)Sq * Sq, nullptr, nullptr, nullptr,
        lsum, nullptr, Sq, inv_sqrt_h, Hh, 1);
    gemm_bf16_nt<<<dim3(Sq / 128, Sq / 128, HB), 128, GSMEM_TOTAL, s1>>>(
        qk + qkoffB, 1024, (long)Sq * 1024, qk + qkoffB + 512, 1024, (long)Sq * 1024,
        pb + poffB, Sq, (long)Sq * Sq, nullptr, nullptr, nullptr,
        lsum + HB * Sq, nullptr, Sq, inv_sqrt_h, Hh, 1);

    // ---- PV (needs vT) ----
    cudaStreamWaitEvent(0, evV, 0);
    cudaStreamWaitEvent(s1, evV, 0);
    gemm_bf16_nt<<<dim3(Sq / 128, Hh / 128, HB), 128, GSMEM_TOTAL>>>(
        pb, Sq, (long)Sq * Sq, vTb, MS, Sq, ctxb, Hh, (long)Sq * Hh,
        nullptr, nullptr, nullptr, nullptr, lsum, Sq, 1.f, Sq, 1);
    gemm_bf16_nt<<<dim3(Sq / 128, Hh / 128, HB), 128, GSMEM_TOTAL, s1>>>(
        pb + poffB, Sq, (long)Sq * Sq, vTb + HB * Sq, MS, Sq,
        ctxb + coffB, Hh, (long)Sq * Hh,
        nullptr, nullptr, nullptr, nullptr, lsum + HB * Sq, Sq, 1.f, Sq, 1);

    // ---- out ----
    gemm_bf16_nt<<<dim3(HB * Sq / 128, Dd / 128, 1), 128, GSMEM_TOTAL>>>(
        ctxb, Hh, 0, wot, Hh, 0, out, Dd, 0, bo, nullptr, x,
        nullptr, nullptr, 0, 1.f, Hh, 0);
    gemm_bf16_nt<<<dim3(HB * Sq / 128, Dd / 128, 1), 128, GSMEM_TOTAL, s1>>>(
        ctxb + coffB, Hh, 0, wot, Hh, 0, out + xoffB, Dd, 0, bo, nullptr, x + xoffB,
        nullptr, nullptr, 0, 1.f, Hh, 0);

    cudaEventRecord(evB, s1);
    cudaStreamWaitEvent(0, evB, 0);
}

// round 16
// speedup vs baseline: 1.2252x; 1.0073x over previous
#include <cuda_runtime.h>
#include <cuda_bf16.h>
#include <cstdint>
#include <math.h>

// Shapes (fixed)
#define Bsz 8
#define Sq  2048
#define Dd  512
#define Hh  512
#define MS  (Bsz * Sq)   // 16384

// ---------------- scratch (device globals) ----------------
__device__ __nv_bfloat16 g_xb  [(long)MS * Dd];
__device__ __nv_bfloat16 g_qk  [(long)MS * 1024];    // q cols 0-511 | k cols 512-1023
__device__ __nv_bfloat16 g_vTb [(long)MS * Hh];      // [Hh, MS]
__device__ __nv_bfloat16 g_ctxb[(long)MS * Hh];
__device__ __nv_bfloat16 g_p   [(long)Bsz * Sq * Sq]; // unnormalized probs (bf16)
__device__ float         g_lsum[MS];                   // per-row exp sums
__device__ __nv_bfloat16 g_wqkt[1024 * Dd];            // WqT | WkT
__device__ __nv_bfloat16 g_wvt[Dd * Hh];
__device__ __nv_bfloat16 g_wot[Dd * Hh];
__device__ float         g_bqk[1024];

// ---------------- helpers ----------------
__device__ __forceinline__ uint32_t smem_u32(const void* p) {
    uint32_t a;
    asm("{ .reg .u64 t; cvta.to.shared.u64 t, %1; cvt.u32.u64 %0, t; }" : "=r"(a) : "l"(p));
    return a;
}
#define LDSM4(r, a)                                                              \
    asm volatile("ldmatrix.sync.aligned.m8n8.x4.shared.b16 {%0,%1,%2,%3}, [%4];" \
                 : "=r"((r)[0]), "=r"((r)[1]), "=r"((r)[2]), "=r"((r)[3])        \
                 : "r"(a))
__device__ __forceinline__ void mma_bf16(float* c, const uint32_t* a,
                                         uint32_t b0, uint32_t b1) {
    asm volatile(
        "mma.sync.aligned.m16n8k16.row.col.f32.bf16.bf16.f32 "
        "{%0,%1,%2,%3}, {%4,%5,%6,%7}, {%8,%9}, {%0,%1,%2,%3};"
        : "+f"(c[0]), "+f"(c[1]), "+f"(c[2]), "+f"(c[3])
        : "r"(a[0]), "r"(a[1]), "r"(a[2]), "r"(a[3]), "r"(b0), "r"(b1));
}
#define CP_ASYNC(dst, src) \
    asm volatile("cp.async.cg.shared.global [%0], [%1], 16;" :: "r"(dst), "l"(src))
#define CP_COMMIT() asm volatile("cp.async.commit_group;" ::: "memory")
#define CP_WAIT(n)  asm volatile("cp.async.wait_group %0;" :: "n"(n) : "memory")

// ============================================================================
// bf16 NT GEMM with fused epilogues.
// BM=BN=128, BK=64, 128 threads (2x2 warps, 64x64 tiles), 3-stage pipeline
// with COMPILE-TIME stage residues (k-loop unrolled by 3; ktiles % 3 == 2).
// ============================================================================
#define RS 144
#define B_OFF  (128 * RS)
#define STAGE  (256 * RS)
#define NSTAGE 3
#define GSMEM_TOTAL (NSTAGE * STAGE)

__device__ __forceinline__ void stage_load(
    uint32_t sbase, const __nv_bfloat16* __restrict__ A, long lda,
    const __nv_bfloat16* __restrict__ B, long ldb, int m0, int n0, int kt, int t)
{
    const int lrow = t >> 3, lch = t & 7;
#pragma unroll
    for (int i = 0; i < 8; i++) {
        const int row = lrow + i * 16;
        CP_ASYNC(sbase + row * RS + lch * 16,
                 A + (long)(m0 + row) * lda + kt + lch * 8);
    }
#pragma unroll
    for (int i = 0; i < 8; i++) {
        const int row = lrow + i * 16;
        CP_ASYNC(sbase + B_OFF + row * RS + lch * 16,
                 B + (long)(n0 + row) * ldb + kt + lch * 8);
    }
}

// One k-tile step with compile-time stage index SIDX (0/1/2).
template<int SIDX>
__device__ __forceinline__ void kt_step(
    uint32_t sb, const uint32_t aB, const uint32_t bB,
    const __nv_bfloat16* __restrict__ A, long lda,
    const __nv_bfloat16* __restrict__ B, long ldb,
    int m0, int n0, int kt, int ktiles, int t,
    float acc[4][8][4])
{
    constexpr uint32_t PRE = ((SIDX + 2) % 3) * STAGE;   // prefetch buffer
    constexpr uint32_t SO  = SIDX * STAGE;               // compute buffer

    if (kt + 2 < ktiles)
        stage_load(sb + PRE, A, lda, B, ldb, m0, n0, (kt + 2) * 64, t);
    CP_COMMIT();

#pragma unroll
    for (int s = 0; s < 4; s++) {
        uint32_t af[4][4], bf[4][4];
#pragma unroll
        for (int mt = 0; mt < 4; mt++)
            LDSM4(af[mt], aB + (SO + mt * (16 * RS) + s * 32));
#pragma unroll
        for (int p = 0; p < 4; p++)
            LDSM4(bf[p], bB + (SO + p * (16 * RS) + s * 32));
#pragma unroll
        for (int mt = 0; mt < 4; mt++)
#pragma unroll
            for (int p = 0; p < 4; p++) {
                mma_bf16(acc[mt][2 * p + 0], af[mt], bf[p][0], bf[p][2]);
                mma_bf16(acc[mt][2 * p + 1], af[mt], bf[p][1], bf[p][3]);
            }
    }

    CP_WAIT(1);
    __syncthreads();
}

__global__ __launch_bounds__(128, 2) void gemm_bf16_nt(
    const __nv_bfloat16* __restrict__ A, long lda, long sA,
    const __nv_bfloat16* __restrict__ B, long ldb, long sB,
    void* __restrict__ Cv, long ldc, long sC,
    const float* __restrict__ biasN, const float* __restrict__ biasM,
    const float* __restrict__ res,
    float* __restrict__ rowsum, const float* __restrict__ rowdiv, long rsStride,
    float alpha, int K, int c_bf16)
{
    extern __shared__ __align__(128) char smem[];
    const uint32_t sb = smem_u32(smem);
    const int t = threadIdx.x;
    const int m0 = blockIdx.x * 128;
    const int n0 = blockIdx.y * 128;

    A += (long)blockIdx.z * sA;
    B += (long)blockIdx.z * sB;
    const float* resz = res ? res + (long)blockIdx.z * sC : nullptr;
    float* rsumz = rowsum ? rowsum + (long)blockIdx.z * rsStride : nullptr;
    const float* rdivz = rowdiv ? rowdiv + (long)blockIdx.z * rsStride : nullptr;

    const int lane = t & 31, w = t >> 5;
    const int wm = w & 1, wn = w >> 1;

    const uint32_t aB = sb + (wm * 64 + (lane & 15)) * RS + (lane >> 4) * 16;
    const uint32_t bB = sb + B_OFF + (wn * 64 + (lane & 15)) * RS + (lane >> 4) * 16;

    float acc[4][8][4];
#pragma unroll
    for (int i = 0; i < 4; i++)
#pragma unroll
        for (int j = 0; j < 8; j++)
#pragma unroll
            for (int r = 0; r < 4; r++) acc[i][j][r] = 0.f;

    const int ktiles = K / 64;   // 8 or 32: always ktiles % 3 == 2
    stage_load(sb, A, lda, B, ldb, m0, n0, 0, t);
    CP_COMMIT();
    stage_load(sb + STAGE, A, lda, B, ldb, m0, n0, 64, t);
    CP_COMMIT();
    CP_WAIT(1);
    __syncthreads();

    int kt = 0;
#pragma unroll 1
    while (kt + 3 <= ktiles) {
        kt_step<0>(sb, aB, bB, A, lda, B, ldb, m0, n0, kt + 0, ktiles, t, acc);
        kt_step<1>(sb, aB, bB, A, lda, B, ldb, m0, n0, kt + 1, ktiles, t, acc);
        kt_step<2>(sb, aB, bB, A, lda, B, ldb, m0, n0, kt + 2, ktiles, t, acc);
        kt += 3;
    }
    // remainder: exactly 2 tiles (kt % 3 == 0 here), stages 0 then 1
    kt_step<0>(sb, aB, bB, A, lda, B, ldb, m0, n0, kt + 0, ktiles, t, acc);
    kt_step<1>(sb, aB, bB, A, lda, B, ldb, m0, n0, kt + 1, ktiles, t, acc);

    const int gcol0 = (lane & 3) * 2;
    const int grow  = lane >> 2;

    if (rsumz) {
        __nv_bfloat16* C = (__nv_bfloat16*)Cv + (long)blockIdx.z * sC;
#pragma unroll
        for (int mt = 0; mt < 4; mt++) {
            const long row = m0 + wm * 64 + mt * 16 + grow;
            float rs0 = 0.f, rs1 = 0.f;
#pragma unroll
            for (int nt = 0; nt < 8; nt++) {
                const int col = n0 + wn * 64 + nt * 8 + gcol0;
                const float e00 = __expf(acc[mt][nt][0] * alpha);
                const float e01 = __expf(acc[mt][nt][1] * alpha);
                const float e10 = __expf(acc[mt][nt][2] * alpha);
                const float e11 = __expf(acc[mt][nt][3] * alpha);
                rs0 += e00 + e01;
                rs1 += e10 + e11;
                *(__nv_bfloat162*)(C + row * ldc + col) =
                    __float22bfloat162_rn(make_float2(e00, e01));
                *(__nv_bfloat162*)(C + (row + 8) * ldc + col) =
                    __float22bfloat162_rn(make_float2(e10, e11));
            }
            rs0 += __shfl_xor_sync(0xffffffffu, rs0, 1);
            rs0 += __shfl_xor_sync(0xffffffffu, rs0, 2);
            rs1 += __shfl_xor_sync(0xffffffffu, rs1, 1);
            rs1 += __shfl_xor_sync(0xffffffffu, rs1, 2);
            if ((lane & 3) == 0) {
                atomicAdd(rsumz + row, rs0);
                atomicAdd(rsumz + row + 8, rs1);
            }
        }
        return;
    }

#pragma unroll
    for (int mt = 0; mt < 4; mt++) {
        const long row = m0 + wm * 64 + mt * 16 + grow;
        const float bm0 = biasM ? biasM[row] : 0.f;
        const float bm1 = biasM ? biasM[row + 8] : 0.f;
        const float iv0 = rdivz ? __fdividef(1.f, rdivz[row]) : 1.f;
        const float iv1 = rdivz ? __fdividef(1.f, rdivz[row + 8]) : 1.f;
#pragma unroll
        for (int nt = 0; nt < 8; nt++) {
            const int col = n0 + wn * 64 + nt * 8 + gcol0;
            float2 v0, v1;
            v0.x = acc[mt][nt][0] * alpha * iv0 + bm0;
            v0.y = acc[mt][nt][1] * alpha * iv0 + bm0;
            v1.x = acc[mt][nt][2] * alpha * iv1 + bm1;
            v1.y = acc[mt][nt][3] * alpha * iv1 + bm1;
            if (biasN) {
                const float2 bb = *(const float2*)(biasN + col);
                v0.x += bb.x; v0.y += bb.y; v1.x += bb.x; v1.y += bb.y;
            }
            if (resz) {
                const float2 r0 = *(const float2*)(resz + row * ldc + col);
                const float2 r1 = *(const float2*)(resz + (row + 8) * ldc + col);
                v0.x += r0.x; v0.y += r0.y; v1.x += r1.x; v1.y += r1.y;
            }
            if (c_bf16) {
                __nv_bfloat16* C = (__nv_bfloat16*)Cv + (long)blockIdx.z * sC;
                *(__nv_bfloat162*)(C + row * ldc + col) = __float22bfloat162_rn(v0);
                *(__nv_bfloat162*)(C + (row + 8) * ldc + col) = __float22bfloat162_rn(v1);
            } else {
                float* C = (float*)Cv + (long)blockIdx.z * sC;
                *(float2*)(C + row * ldc + col) = v0;
                *(float2*)(C + (row + 8) * ldc + col) = v1;
            }
        }
    }
}

// ---------------- 4x 512x512 transpose -> bf16, one launch ----------------
struct TPtrs {
    const float* w[4];
    __nv_bfloat16* wt[4];
};
__global__ __launch_bounds__(256) void transpose_all(TPtrs p)
{
    const float* W = p.w[blockIdx.z];
    __nv_bfloat16* Wt = p.wt[blockIdx.z];
    __shared__ float tile[32][33];
    const int tx = threadIdx.x, ty = threadIdx.y;
    int x = blockIdx.x * 32 + tx;
    int y = blockIdx.y * 32 + ty;
#pragma unroll
    for (int i = 0; i < 4; i++)
        tile[ty + i * 8][tx] = W[(y + i * 8) * 512 + x];
    __syncthreads();
    x = blockIdx.y * 32 + tx;
    y = blockIdx.x * 32 + ty;
#pragma unroll
    for (int i = 0; i < 4; i++)
        Wt[(y + i * 8) * 512 + x] = __float2bfloat16_rn(tile[tx][ty + i * 8]);
}

// ---------------- prep: cvt x -> bf16, zero lsum, concat biases ----------------
__global__ __launch_bounds__(256) void prep_misc(
    const float* __restrict__ in, __nv_bfloat16* __restrict__ out, long n4,
    float* __restrict__ zbuf, long zn,
    const float* __restrict__ bq, const float* __restrict__ bk,
    float* __restrict__ bqk)
{
    const long i = (long)blockIdx.x * blockDim.x + threadIdx.x;
    if (i < n4) {
        float4 v = ((const float4*)in)[i];
        *(__nv_bfloat162*)(out + i * 4)     = __float22bfloat162_rn(make_float2(v.x, v.y));
        *(__nv_bfloat162*)(out + i * 4 + 2) = __float22bfloat162_rn(make_float2(v.z, v.w));
    }
    if (i < zn) zbuf[i] = 0.f;
    if (i < 1024) bqk[i] = (i < 512) ? bq[i] : bk[i - 512];
}

// ---------------- launch ----------------
extern "C" void kernel_launch(void* const* d_in, const int* in_sizes, int n_in,
                              void* d_out, int out_size)
{
    const float* x  = (const float*)d_in[0];
    const float* Wq = (const float*)d_in[1];
    const float* bq = (const float*)d_in[2];
    const float* Wk = (const float*)d_in[3];
    const float* bk = (const float*)d_in[4];
    const float* Wv = (const float*)d_in[5];
    const float* bv = (const float*)d_in[6];
    const float* Wo = (const float*)d_in[7];
    const float* bo = (const float*)d_in[8];
    float* out = (float*)d_out;

    __nv_bfloat16 *xb, *qk, *vTb, *ctxb, *pb, *wqkt, *wvt, *wot;
    float *lsum, *bqk;
    cudaGetSymbolAddress((void**)&xb,   g_xb);
    cudaGetSymbolAddress((void**)&qk,   g_qk);
    cudaGetSymbolAddress((void**)&vTb,  g_vTb);
    cudaGetSymbolAddress((void**)&ctxb, g_ctxb);
    cudaGetSymbolAddress((void**)&pb,   g_p);
    cudaGetSymbolAddress((void**)&lsum, g_lsum);
    cudaGetSymbolAddress((void**)&wqkt, g_wqkt);
    cudaGetSymbolAddress((void**)&wvt,  g_wvt);
    cudaGetSymbolAddress((void**)&wot,  g_wot);
    cudaGetSymbolAddress((void**)&bqk,  g_bqk);

    static cudaStream_t s1 = nullptr, s2 = nullptr;
    static cudaEvent_t evFork, evT, evPrep, evV, evB;
    if (!s1) {
        cudaFuncSetAttribute(gemm_bf16_nt,
                             cudaFuncAttributeMaxDynamicSharedMemorySize, GSMEM_TOTAL);
        cudaStreamCreateWithFlags(&s1, cudaStreamNonBlocking);
        cudaStreamCreateWithFlags(&s2, cudaStreamNonBlocking);
        cudaEventCreateWithFlags(&evFork, cudaEventDisableTiming);
        cudaEventCreateWithFlags(&evT,    cudaEventDisableTiming);
        cudaEventCreateWithFlags(&evPrep, cudaEventDisableTiming);
        cudaEventCreateWithFlags(&evV,    cudaEventDisableTiming);
        cudaEventCreateWithFlags(&evB,    cudaEventDisableTiming);
    }

    const float inv_sqrt_h = 1.f / sqrtf((float)Hh);
    const long HB = 4;                  // batches per half
    const long xoffB  = HB * Sq * Dd;
    const long qkoffB = HB * Sq * 1024;
    const long poffB  = HB * Sq * Sq;
    const long coffB  = HB * Sq * Hh;

    // ---- prep: fork s2 from stream 0 FIRST (capture rule), then overlap ----
    cudaEventRecord(evFork, 0);
    cudaStreamWaitEvent(s2, evFork, 0);
    {
        TPtrs tp;
        tp.w[0] = Wq; tp.w[1] = Wk; tp.w[2] = Wv; tp.w[3] = Wo;
        tp.wt[0] = wqkt; tp.wt[1] = wqkt + 512 * 512; tp.wt[2] = wvt; tp.wt[3] = wot;
        transpose_all<<<dim3(16, 16, 4), dim3(32, 8), 0, s2>>>(tp);
        cudaEventRecord(evT, s2);
        const long n4 = (long)MS * Dd / 4;
        prep_misc<<<(n4 + 255) / 256, 256>>>(x, xb, n4, lsum, MS, bq, bk, bqk);
    }
    cudaStreamWaitEvent(0, evT, 0);
    cudaEventRecord(evPrep, 0);
    cudaStreamWaitEvent(s1, evPrep, 0);
    cudaStreamWaitEvent(s2, evPrep, 0);

    // ---- projections: qkA on s0, qkB on s1, vT on s2 ----
    gemm_bf16_nt<<<dim3(HB * Sq / 128, 1024 / 128, 1), 128, GSMEM_TOTAL>>>(
        xb, Dd, 0, wqkt, Dd, 0, qk, 1024, 0, bqk, nullptr, nullptr,
        nullptr, nullptr, 0, 1.f, Dd, 1);
    gemm_bf16_nt<<<dim3(HB * Sq / 128, 1024 / 128, 1), 128, GSMEM_TOTAL, s1>>>(
        xb + xoffB, Dd, 0, wqkt, Dd, 0, qk + qkoffB, 1024, 0, bqk, nullptr, nullptr,
        nullptr, nullptr, 0, 1.f, Dd, 1);
    gemm_bf16_nt<<<dim3(Hh / 128, MS / 128, 1), 128, GSMEM_TOTAL, s2>>>(
        wvt, Dd, 0, xb, Dd, 0, vTb, MS, 0, nullptr, bv, nullptr,
        nullptr, nullptr, 0, 1.f, Dd, 1);
    cudaEventRecord(evV, s2);

    // ---- scores (stream-local after qk halves) ----
    gemm_bf16_nt<<<dim3(Sq / 128, Sq / 128, HB), 128, GSMEM_TOTAL>>>(
        qk, 1024, (long)Sq * 1024, qk + 512, 1024, (long)Sq * 1024,
        pb, Sq, (long)Sq * Sq, nullptr, nullptr, nullptr,
        lsum, nullptr, Sq, inv_sqrt_h, Hh, 1);
    gemm_bf16_nt<<<dim3(Sq / 128, Sq / 128, HB), 128, GSMEM_TOTAL, s1>>>(
        qk + qkoffB, 1024, (long)Sq * 1024, qk + qkoffB + 512, 1024, (long)Sq * 1024,
        pb + poffB, Sq, (long)Sq * Sq, nullptr, nullptr, nullptr,
        lsum + HB * Sq, nullptr, Sq, inv_sqrt_h, Hh, 1);

    // ---- PV (needs vT) ----
    cudaStreamWaitEvent(0, evV, 0);
    cudaStreamWaitEvent(s1, evV, 0);
    gemm_bf16_nt<<<dim3(Sq / 128, Hh / 128, HB), 128, GSMEM_TOTAL>>>(
        pb, Sq, (long)Sq * Sq, vTb, MS, Sq, ctxb, Hh, (long)Sq * Hh,
        nullptr, nullptr, nullptr, nullptr, lsum, Sq, 1.f, Sq, 1);
    gemm_bf16_nt<<<dim3(Sq / 128, Hh / 128, HB), 128, GSMEM_TOTAL, s1>>>(
        pb + poffB, Sq, (long)Sq * Sq, vTb + HB * Sq, MS, Sq,
        ctxb + coffB, Hh, (long)Sq * Hh,
        nullptr, nullptr, nullptr, nullptr, lsum + HB * Sq, Sq, 1.f, Sq, 1);

    // ---- out ----
    gemm_bf16_nt<<<dim3(HB * Sq / 128, Dd / 128, 1), 128, GSMEM_TOTAL>>>(
        ctxb, Hh, 0, wot, Hh, 0, out, Dd, 0, bo, nullptr, x,
        nullptr, nullptr, 0, 1.f, Hh, 0);
    gemm_bf16_nt<<<dim3(HB * Sq / 128, Dd / 128, 1), 128, GSMEM_TOTAL, s1>>>(
        ctxb + coffB, Hh, 0, wot, Hh, 0, out + xoffB, Dd, 0, bo, nullptr, x + xoffB,
        nullptr, nullptr, 0, 1.f, Hh, 0);

    cudaEventRecord(evB, s1);
    cudaStreamWaitEvent(0, evB, 0);
}